// round 9
// baseline (speedup 1.0000x reference)
#include <cuda_runtime.h>
#include <cuda_bf16.h>
#include <math.h>
#include <stdint.h>

#define B_    2
#define H_    16
#define BH    32
#define T_    2048
#define S_    2048
#define D_    64
#define U_SEL 614
#define SEL_STRIDE 640
#define SCALE 0.125f
#define LOGS  7.624618986159398
#define QSTRIDE_A 68

__device__ float g_kl[BH * T_];
__device__ int   g_sel[BH * SEL_STRIDE];

// bf16 split planes (pre-swizzled 128B rows), ~8.4MB each
__device__ __nv_bfloat16 g_qp0[BH * T_ * D_];
__device__ __nv_bfloat16 g_qp1[BH * T_ * D_];
__device__ __nv_bfloat16 g_qp2[BH * T_ * D_];
__device__ __nv_bfloat16 g_kp0[BH * S_ * D_];
__device__ __nv_bfloat16 g_kp1[BH * S_ * D_];
__device__ __nv_bfloat16 g_kp2[BH * S_ * D_];

// ---------------------------------------------------------------------------
// helpers
// ---------------------------------------------------------------------------
__device__ __forceinline__ uint32_t smem_u32(const void* p) {
    return (uint32_t)__cvta_generic_to_shared(p);
}
__device__ __forceinline__ void cp_async16(uint32_t dst, const void* src) {
    asm volatile("cp.async.cg.shared.global [%0], [%1], 16;\n" :: "r"(dst), "l"(src));
}
__device__ __forceinline__ void cp_commit() {
    asm volatile("cp.async.commit_group;\n");
}
template <int N>
__device__ __forceinline__ void cp_wait() {
    asm volatile("cp.async.wait_group %0;\n" :: "n"(N));
}

// m16n8k16 bf16 HMMA (family-generic PTX, sm_80+)
__device__ __forceinline__ void hmma(float* d, const uint32_t* a, const uint32_t* b)
{
    asm volatile(
        "mma.sync.aligned.m16n8k16.row.col.f32.bf16.bf16.f32 "
        "{%0,%1,%2,%3}, {%4,%5,%6,%7}, {%8,%9}, {%0,%1,%2,%3};"
        : "+f"(d[0]), "+f"(d[1]), "+f"(d[2]), "+f"(d[3])
        : "r"(a[0]), "r"(a[1]), "r"(a[2]), "r"(a[3]), "r"(b[0]), "r"(b[1]));
}

// packed f32x2 (attn, proven to compile on this target)
__device__ __forceinline__ unsigned long long pack2(float lo, float hi) {
    unsigned long long r;
    asm("mov.b64 %0, {%1, %2};" : "=l"(r) : "f"(lo), "f"(hi));
    return r;
}
__device__ __forceinline__ void ffma2(unsigned long long& d,
                                      unsigned long long a, unsigned long long b) {
    asm("fma.rn.f32x2 %0, %1, %2, %3;" : "=l"(d) : "l"(a), "l"(b), "l"(d));
}
__device__ __forceinline__ float2 unpack2(unsigned long long a) {
    float lo, hi;
    asm("mov.b64 {%0, %1}, %2;" : "=f"(lo), "=f"(hi) : "l"(a));
    return make_float2(lo, hi);
}

// ---------------------------------------------------------------------------
// Phase 0: split q,k into 3 bf16 planes each, stored with 16B-chunk XOR
// swizzle within each 128B row (row index mod 8).
// ---------------------------------------------------------------------------
#define NCH (BH * T_ * D_ / 8)   // 16B output chunks per tensor = 524288

__global__ __launch_bounds__(256)
void split_kernel(const float* __restrict__ q, const float* __restrict__ k)
{
    int idx = blockIdx.x * 256 + threadIdx.x;
    const float* src;
    __nv_bfloat16 *p1, *p2, *p3;
    if (idx < NCH) { src = q; p1 = g_qp0; p2 = g_qp1; p3 = g_qp2; }
    else { idx -= NCH; src = k; p1 = g_kp0; p2 = g_kp1; p3 = g_kp2; }

    int row = idx >> 3, c = idx & 7;
    size_t dst = (size_t)row * 64 + (size_t)((c ^ (row & 7)) * 8);
    const float4* s4 = (const float4*)src + (size_t)row * 16 + c * 2;
    float4 f0 = s4[0], f1 = s4[1];
    float v[8] = {f0.x, f0.y, f0.z, f0.w, f1.x, f1.y, f1.z, f1.w};

    unsigned short h1[8], h2[8], h3[8];
#pragma unroll
    for (int i = 0; i < 8; i++) {
        float x = v[i];
        __nv_bfloat16 b1 = __float2bfloat16(x);
        float r = x - __bfloat162float(b1);
        __nv_bfloat16 b2 = __float2bfloat16(r);
        float r2 = r - __bfloat162float(b2);
        __nv_bfloat16 b3 = __float2bfloat16(r2);
        h1[i] = __bfloat16_as_ushort(b1);
        h2[i] = __bfloat16_as_ushort(b2);
        h3[i] = __bfloat16_as_ushort(b3);
    }
#define PACKU4(h) make_uint4( \
        (uint32_t)h[0] | ((uint32_t)h[1] << 16), (uint32_t)h[2] | ((uint32_t)h[3] << 16), \
        (uint32_t)h[4] | ((uint32_t)h[5] << 16), (uint32_t)h[6] | ((uint32_t)h[7] << 16))
    *(uint4*)(p1 + dst) = PACKU4(h1);
    *(uint4*)(p2 + dst) = PACKU4(h2);
    *(uint4*)(p3 + dst) = PACKU4(h3);
#undef PACKU4
}

// ---------------------------------------------------------------------------
// Phase 1: HMMA bf16 3-split QK^T + online-softmax KL.
// CTA: 128 queries x S in 32 tiles of 64 keys. 8 warps, warp = 16 rows x all
// 64 cols (8 n-frags). 6 split-terms per k16-step. Double-prec online stats.
// smem: Q planes 3*16KB + K tile 2 bufs * 3 * 8KB = 96KB. 2 CTAs/SM.
// ---------------------------------------------------------------------------
#define KLN_T 32   // S tiles
#define QPL 16384
#define KPL 8192
#define KBUF 24576
#define KL_SMEM 98304

__global__ __launch_bounds__(256, 2)
void kl_kernel()
{
    extern __shared__ char sm[];
    char* Qs = sm;            // plane p at + p*QPL
    char* Ks = sm + 3 * QPL;  // buf b at + b*KBUF, plane p at + p*KPL

    const int tid = threadIdx.x;
    const int w = tid >> 5, lane = tid & 31;
    const int g = lane >> 2, t4 = lane & 3;
    const int bh = blockIdx.y;
    const int q0 = blockIdx.x * 128;

    const char* gq[3] = {(const char*)g_qp0, (const char*)g_qp1, (const char*)g_qp2};
    const char* gk[3] = {(const char*)g_kp0, (const char*)g_kp1, (const char*)g_kp2};
    const size_t qrow0 = ((size_t)bh * T_ + q0) * 128;   // bytes
    const size_t krow0 = (size_t)bh * S_ * 128;

    // load Q planes (3*1024 chunks of 16B)
    for (int i = tid; i < 3072; i += 256) {
        int p = i >> 10, r = i & 1023;
        cp_async16(smem_u32(Qs + p * QPL + r * 16), gq[p] + qrow0 + (size_t)r * 16);
    }
    // prefetch K tile 0
    for (int i = tid; i < 1536; i += 256) {
        int p = i >> 9, r = i & 511;
        cp_async16(smem_u32(Ks + p * KPL + r * 16), gk[p] + krow0 + (size_t)r * 16);
    }
    cp_commit();

    float  m_run[2] = {-1e30f, -1e30f};
    double Zr[2] = {0.0, 0.0}, Ar[2] = {0.0, 0.0};
    const int r0 = 16 * w + g;   // row in tile; r1 = r0 + 8
    const int wb = t4 * 4;       // byte within 16B chunk

    for (int n = 0; n < KLN_T; n++) {
        const int buf = n & 1;
        if (n + 1 < KLN_T) {
            char* dst = Ks + ((n + 1) & 1) * KBUF;
            const size_t src0 = krow0 + (size_t)(n + 1) * 64 * 128;
            for (int i = tid; i < 1536; i += 256) {
                int p = i >> 9, r = i & 511;
                cp_async16(smem_u32(dst + p * KPL + r * 16), gk[p] + src0 + (size_t)r * 16);
            }
            cp_commit();
            cp_wait<1>();
        } else {
            cp_wait<0>();
        }
        __syncthreads();

        const char* Kb = Ks + buf * KBUF;

        float acc[8][4];
#pragma unroll
        for (int j = 0; j < 8; j++)
#pragma unroll
            for (int c = 0; c < 4; c++) acc[j][c] = 0.f;

#pragma unroll
        for (int ks = 0; ks < 4; ks++) {
            const int ch0 = 2 * ks, ch1 = 2 * ks + 1;
            uint32_t a[3][4];
#pragma unroll
            for (int p = 0; p < 3; p++) {
                const char* base = Qs + p * QPL;
                a[p][0] = *(const uint32_t*)(base + r0 * 128 + ((ch0 ^ (r0 & 7)) << 4) + wb);
                a[p][1] = *(const uint32_t*)(base + (r0 + 8) * 128 + ((ch0 ^ (r0 & 7)) << 4) + wb);
                a[p][2] = *(const uint32_t*)(base + r0 * 128 + ((ch1 ^ (r0 & 7)) << 4) + wb);
                a[p][3] = *(const uint32_t*)(base + (r0 + 8) * 128 + ((ch1 ^ (r0 & 7)) << 4) + wb);
            }
#pragma unroll
            for (int j = 0; j < 8; j++) {
                const int nr = 8 * j + g;
                uint32_t b[3][2];
#pragma unroll
                for (int p = 0; p < 3; p++) {
                    const char* base = Kb + p * KPL;
                    b[p][0] = *(const uint32_t*)(base + nr * 128 + ((ch0 ^ (nr & 7)) << 4) + wb);
                    b[p][1] = *(const uint32_t*)(base + nr * 128 + ((ch1 ^ (nr & 7)) << 4) + wb);
                }
                hmma(acc[j], a[0], b[0]);   // q1*k1
                hmma(acc[j], a[0], b[1]);   // q1*k2
                hmma(acc[j], a[1], b[0]);   // q2*k1
                hmma(acc[j], a[0], b[2]);   // q1*k3
                hmma(acc[j], a[2], b[0]);   // q3*k1
                hmma(acc[j], a[1], b[1]);   // q2*k2
            }
        }

        // epilogue: per-row (2 rows/thread) chunk softmax stats over 64 cols
#pragma unroll
        for (int rr = 0; rr < 2; rr++) {
            float sv[16];
            float mc = -1e30f;
#pragma unroll
            for (int j = 0; j < 8; j++) {
#pragma unroll
                for (int c = 0; c < 2; c++) {
                    float s = fminf(fmaxf(acc[j][2 * rr + c] * SCALE, -50.f), 50.f);
                    sv[2 * j + c] = s;
                    mc = fmaxf(mc, s);
                }
            }
            mc = fmaxf(mc, __shfl_xor_sync(0xffffffffu, mc, 1));
            mc = fmaxf(mc, __shfl_xor_sync(0xffffffffu, mc, 2));
            float zc = 0.f, ac = 0.f;
#pragma unroll
            for (int i = 0; i < 16; i++) {
                float p = sv[i] - mc;
                float e = __expf(p);
                zc += e;
                ac = fmaf(e, p, ac);
            }
            zc += __shfl_xor_sync(0xffffffffu, zc, 1);
            zc += __shfl_xor_sync(0xffffffffu, zc, 2);
            ac += __shfl_xor_sync(0xffffffffu, ac, 1);
            ac += __shfl_xor_sync(0xffffffffu, ac, 2);

            float newm = fmaxf(m_run[rr], mc);
            double d1 = (double)m_run[rr] - (double)newm;
            double d2 = (double)mc - (double)newm;
            double f1 = exp(d1), f2 = exp(d2);
            double Zn = f1 * Zr[rr] + f2 * (double)zc;
            double An = f1 * (Ar[rr] + d1 * Zr[rr]) + f2 * ((double)ac + d2 * (double)zc);
            Zr[rr] = Zn; Ar[rr] = An; m_run[rr] = newm;
        }
        __syncthreads();   // all reads of Kb done before its buffer is rewritten
    }

    if (t4 == 0) {
#pragma unroll
        for (int rr = 0; rr < 2; rr++) {
            int row = r0 + 8 * rr;
            double kl = Ar[rr] / Zr[rr] - log(Zr[rr]) + LOGS;
            g_kl[bh * T_ + q0 + row] = (float)kl;
        }
    }
}

// ---------------------------------------------------------------------------
// Phase 2: exact top-u via 8-bit MSB radix select, stable low-index tie-break.
// ---------------------------------------------------------------------------
__global__ void topk_kernel(int u)
{
    const int bh = blockIdx.x;
    const int tid = threadIdx.x;   // 256
    __shared__ unsigned keys[T_];
    __shared__ int hist[256];
    __shared__ int sums[256];
    __shared__ int sh_digit, sh_need;

    for (int t = tid; t < T_; t += 256) {
        unsigned b = __float_as_uint(g_kl[bh * T_ + t]);
        keys[t] = (b & 0x80000000u) ? ~b : (b | 0x80000000u);
    }
    __syncthreads();

    unsigned prefix = 0u, pmask = 0u;
    int need = u;
    for (int shift = 24; shift >= 0; shift -= 8) {
        hist[tid] = 0;
        __syncthreads();
        for (int t = tid; t < T_; t += 256) {
            unsigned kk = keys[t];
            if ((kk & pmask) == prefix)
                atomicAdd(&hist[(kk >> shift) & 255u], 1);
        }
        __syncthreads();
        if (tid == 0) {
            int cum = 0, d = 255;
            for (; d > 0; d--) {
                if (cum + hist[d] >= need) break;
                cum += hist[d];
            }
            sh_digit = d;
            sh_need  = need - cum;
        }
        __syncthreads();
        prefix |= ((unsigned)sh_digit) << shift;
        pmask  |= (255u << shift);
        need = sh_need;
        __syncthreads();
    }
    const unsigned thr = prefix;
    const int tie_take = need;

    const int base = tid * (T_ / 256);
    bool gtf[8], eqf[8];
    int cnt_eq = 0;
#pragma unroll
    for (int i = 0; i < 8; i++) {
        unsigned kk = keys[base + i];
        gtf[i] = (kk > thr);
        eqf[i] = (kk == thr);
        cnt_eq += eqf[i] ? 1 : 0;
    }
    sums[tid] = cnt_eq; __syncthreads();
    for (int off = 1; off < 256; off <<= 1) {
        int x = (tid >= off) ? sums[tid - off] : 0;
        __syncthreads();
        sums[tid] += x;
        __syncthreads();
    }
    int eqr = sums[tid] - cnt_eq;
    __syncthreads();

    bool self[8];
    int cnt_sel = 0;
#pragma unroll
    for (int i = 0; i < 8; i++) {
        bool s = gtf[i] || (eqf[i] && (eqr < tie_take));
        if (eqf[i]) eqr++;
        self[i] = s;
        cnt_sel += s ? 1 : 0;
    }
    sums[tid] = cnt_sel; __syncthreads();
    for (int off = 1; off < 256; off <<= 1) {
        int x = (tid >= off) ? sums[tid - off] : 0;
        __syncthreads();
        sums[tid] += x;
        __syncthreads();
    }
    int pos = sums[tid] - cnt_sel;
#pragma unroll
    for (int i = 0; i < 8; i++)
        if (self[i]) g_sel[bh * SEL_STRIDE + pos++] = base + i;
}

// ---------------------------------------------------------------------------
// Phase 3: sparse attention (proven). 64q x 64k tiles, 4x4 thread tile,
// FFMA2 for QK (row pairs) and PV (output pairs).
// ---------------------------------------------------------------------------
__global__ __launch_bounds__(256, 3)
void attn_kernel(const float* __restrict__ q, const float* __restrict__ k,
                 const float* __restrict__ v, float* __restrict__ out, int u)
{
    extern __shared__ char smemraw[];
    float*  Qt  = (float*)smemraw;
    float4* KP4 = (float4*)(smemraw + 64 * QSTRIDE_A * 4);
    float4* Vs4 = KP4 + 1024;

    const int tid = threadIdx.x;
    const int tx = tid & 15, ty = tid >> 4;
    const int bh = blockIdx.y;
    const int q0 = blockIdx.x * 64;

    const int*    selp = g_sel + bh * SEL_STRIDE;
    const float4* kb4  = (const float4*)(k + (size_t)bh * S_ * D_);
    const float4* vb4  = (const float4*)(v + (size_t)bh * S_ * D_);
    const float4* qg4  = (const float4*)q;

    for (int lin = tid; lin < 1024; lin += 256) {
        int row = lin >> 4, dv = lin & 15;
        int qi = q0 + row;
        float4 vq = make_float4(0.f, 0.f, 0.f, 0.f);
        if (qi < u) vq = qg4[((size_t)bh * T_ + selp[qi]) * 16 + dv];
        float* dst = Qt + (4 * dv) * QSTRIDE_A + row;
        dst[0 * QSTRIDE_A] = vq.x;
        dst[1 * QSTRIDE_A] = vq.y;
        dst[2 * QSTRIDE_A] = vq.z;
        dst[3 * QSTRIDE_A] = vq.w;
    }

    float row_m[4], row_Z[4];
    unsigned long long Oxy[4], Ozw[4];
#pragma unroll
    for (int i = 0; i < 4; i++) {
        row_m[i] = -1e30f; row_Z[i] = 0.f;
        Oxy[i] = 0ULL; Ozw[i] = 0ULL;
    }

    for (int kt = 0; kt < S_ / 64; kt++) {
        __syncthreads();
        const float4* kp4 = kb4 + (size_t)kt * 64 * 16;
        const float4* vp4 = vb4 + (size_t)kt * 64 * 16;
        for (int lin = tid; lin < 1024; lin += 256) {
            int r = lin >> 4, dv = lin & 15;
            KP4[(r << 4) + (dv ^ (r & 15))] = kp4[lin];
            Vs4[lin] = vp4[lin];
        }
        __syncthreads();

        unsigned long long acc2[2][4];
#pragma unroll
        for (int p = 0; p < 2; p++)
#pragma unroll
            for (int j = 0; j < 4; j++) acc2[p][j] = 0ULL;

#pragma unroll 4
        for (int dv = 0; dv < 16; dv++) {
            const float4* Kbase = KP4 + (tx << 4) + (dv ^ tx);
            float4 kv[4];
#pragma unroll
            for (int j = 0; j < 4; j++) kv[j] = Kbase[j << 8];

            const float* Qb = Qt + (4 * dv) * QSTRIDE_A + 4 * ty;
#pragma unroll
            for (int dsub = 0; dsub < 4; dsub++) {
                float4 qa = *(const float4*)(Qb + dsub * QSTRIDE_A);
                unsigned long long q01 = pack2(qa.x, qa.y);
                unsigned long long q23 = pack2(qa.z, qa.w);
#pragma unroll
                for (int j = 0; j < 4; j++) {
                    float ks = ((const float*)&kv[j])[dsub];
                    unsigned long long kb2 = pack2(ks, ks);
                    ffma2(acc2[0][j], q01, kb2);
                    ffma2(acc2[1][j], q23, kb2);
                }
            }
        }

        float p[4][4];
#pragma unroll
        for (int i = 0; i < 4; i++) {
            const int pp = i >> 1;
            float sv[4];
#pragma unroll
            for (int j = 0; j < 4; j++) {
                float2 uu = unpack2(acc2[pp][j]);
                sv[j] = (i & 1) ? uu.y : uu.x;
            }
            float tmax = -1e30f;
#pragma unroll
            for (int j = 0; j < 4; j++) {
                float s = fminf(fmaxf(sv[j] * SCALE, -50.f), 50.f);
                sv[j] = s;
                tmax = fmaxf(tmax, s);
            }
#pragma unroll
            for (int o = 8; o >= 1; o >>= 1)
                tmax = fmaxf(tmax, __shfl_xor_sync(0xffffffffu, tmax, o));

            float newm = fmaxf(row_m[i], tmax);
            float f = __expf(row_m[i] - newm);
            float zt = 0.f;
#pragma unroll
            for (int j = 0; j < 4; j++) {
                float e = __expf(sv[j] - newm);
                p[i][j] = e;
                zt += e;
            }
#pragma unroll
            for (int o = 8; o >= 1; o >>= 1)
                zt += __shfl_xor_sync(0xffffffffu, zt, o);

            row_Z[i] = row_Z[i] * f + zt;
            unsigned long long f2 = pack2(f, f);
            asm("mul.rn.f32x2 %0, %0, %1;" : "+l"(Oxy[i]) : "l"(f2));
            asm("mul.rn.f32x2 %0, %0, %1;" : "+l"(Ozw[i]) : "l"(f2));
            row_m[i] = newm;
        }
        __syncthreads();

        float* Pf = (float*)KP4;
#pragma unroll
        for (int i = 0; i < 4; i++)
#pragma unroll
            for (int j = 0; j < 4; j++)
                Pf[((4 * ty + i) << 6) + tx + 16 * j] = p[i][j];
        __syncthreads();

#pragma unroll 4
        for (int kkv = 0; kkv < 16; kkv++) {
            float4 pv[4], vv[4];
#pragma unroll
            for (int i = 0; i < 4; i++) pv[i] = KP4[((4 * ty + i) << 4) + kkv];
#pragma unroll
            for (int m = 0; m < 4; m++) vv[m] = Vs4[((4 * kkv + m) << 4) + tx];
#pragma unroll
            for (int m = 0; m < 4; m++) {
                unsigned long long vxy = pack2(vv[m].x, vv[m].y);
                unsigned long long vzw = pack2(vv[m].z, vv[m].w);
#pragma unroll
                for (int i = 0; i < 4; i++) {
                    float pb = ((const float*)&pv[i])[m];
                    unsigned long long pb2 = pack2(pb, pb);
                    ffma2(Oxy[i], pb2, vxy);
                    ffma2(Ozw[i], pb2, vzw);
                }
            }
        }
    }

#pragma unroll
    for (int i = 0; i < 4; i++) {
        int qi = q0 + 4 * ty + i;
        if (qi < u) {
            int t = selp[qi];
            float inv = 1.0f / row_Z[i];
            float2 oxy = unpack2(Oxy[i]);
            float2 ozw = unpack2(Ozw[i]);
            float4 o = make_float4(oxy.x * inv, oxy.y * inv,
                                   ozw.x * inv, ozw.y * inv);
            float4* op4 = (float4*)(out + ((size_t)bh * T_ + t) * D_);
            op4[tx] = o;
        }
    }
}

// ---------------------------------------------------------------------------
extern "C" void kernel_launch(void* const* d_in, const int* in_sizes, int n_in,
                              void* d_out, int out_size)
{
    (void)in_sizes; (void)n_in;
    const float* q = (const float*)d_in[0];
    const float* k = (const float*)d_in[1];
    const float* v = (const float*)d_in[2];
    float* out = (float*)d_out;

    const int attn_smem = 64 * QSTRIDE_A * 4 + 2 * 1024 * 16;
    cudaFuncSetAttribute(kl_kernel, cudaFuncAttributeMaxDynamicSharedMemorySize,
                         KL_SMEM);
    cudaFuncSetAttribute(attn_kernel, cudaFuncAttributeMaxDynamicSharedMemorySize,
                         attn_smem);

    cudaMemsetAsync(d_out, 0, (size_t)out_size * sizeof(float), 0);

    split_kernel<<<(2 * NCH) / 256, 256>>>(q, k);

    dim3 g1(T_ / 128, BH);
    kl_kernel<<<g1, 256, KL_SMEM>>>();

    topk_kernel<<<BH, 256>>>(U_SEL);

    dim3 g3((U_SEL + 63) / 64, BH);
    attn_kernel<<<g3, 256, attn_smem>>>(q, k, v, out, U_SEL);
}

// round 10
// speedup vs baseline: 1.5092x; 1.5092x over previous
#include <cuda_runtime.h>
#include <math.h>
#include <stdint.h>

#define B_    2
#define H_    16
#define BH    32
#define T_    2048
#define S_    2048
#define D_    64
#define U_SEL 614        // max(int(min(0.4*ln(2048),1024)), int(0.3*2048)) = max(3,614)
#define SEL_STRIDE 640
#define SCALE 0.125f     // 1/sqrt(64)
#define LOGS  7.624618986159398  // log(2048)
#define SHALF 1024       // S per split half
#define QSTRIDE 132      // Qt row stride (floats), multiple of 4
#define QSTRIDE_A 68     // attn Qt stride

__device__ int    g_sel[BH * SEL_STRIDE];
__device__ float  g_m[2 * BH * T_];
__device__ double g_Zd[2 * BH * T_];
__device__ double g_Ad[2 * BH * T_];

// ---------------------------------------------------------------------------
// helpers
// ---------------------------------------------------------------------------
__device__ __forceinline__ uint32_t smem_u32(const void* p) {
    return (uint32_t)__cvta_generic_to_shared(p);
}
__device__ __forceinline__ void cp_async16(uint32_t dst, const void* src) {
    asm volatile("cp.async.cg.shared.global [%0], [%1], 16;\n" :: "r"(dst), "l"(src));
}
__device__ __forceinline__ void cp_commit() {
    asm volatile("cp.async.commit_group;\n");
}
template <int N>
__device__ __forceinline__ void cp_wait() {
    asm volatile("cp.async.wait_group %0;\n" :: "n"(N));
}

// packed f32x2 ops (Blackwell): 2 fp32 FMAs per issue slot
__device__ __forceinline__ unsigned long long pack2(float lo, float hi) {
    unsigned long long r;
    asm("mov.b64 %0, {%1, %2};" : "=l"(r) : "f"(lo), "f"(hi));
    return r;
}
__device__ __forceinline__ void ffma2(unsigned long long& d,
                                      unsigned long long a, unsigned long long b) {
    asm("fma.rn.f32x2 %0, %1, %2, %3;" : "=l"(d) : "l"(a), "l"(b), "l"(d));
}
__device__ __forceinline__ float2 unpack2(unsigned long long a) {
    float lo, hi;
    asm("mov.b64 {%0, %1}, %2;" : "=f"(lo), "=f"(hi) : "l"(a));
    return make_float2(lo, hi);
}

// ---------------------------------------------------------------------------
// Phase 1: partial online-softmax KL stats. 128q x 128k tile, 8 rows x 8 cols
// per thread, rows packed in f32x2 pairs (acc2[4][8] u64). Q transposed in
// smem (Qt[d][row]); K double-buffered cp.async, swizzled. 2 CTAs/SM.
// ---------------------------------------------------------------------------
__global__ __launch_bounds__(256, 2)
void kl_kernel(const float* __restrict__ q, const float* __restrict__ k)
{
    extern __shared__ char smemraw[];
    float*  Qt  = (float*)smemraw;                        // 64*132 floats (33792 B)
    float4* Ks4 = (float4*)(smemraw + 64 * QSTRIDE * 4);  // 2*2048 float4 (64 KB)
    double* Zs  = (double*)(smemraw + 64 * QSTRIDE * 4 + 2 * 2048 * 16);
    double* As  = Zs + 128;

    const int tid = threadIdx.x;
    const int tx = tid & 15, ty = tid >> 4;
    const int bh = blockIdx.y;
    const int q0 = blockIdx.x * 128;
    const int sh = blockIdx.z;

    const float4* qp4 = (const float4*)(q + ((size_t)bh * T_ + q0) * D_);
    const float4* kp4 = (const float4*)(k + ((size_t)bh * S_ + sh * SHALF) * D_);

    // transpose Q into Qt[d][row]
    for (int lin = tid; lin < 2048; lin += 256) {
        int row = lin >> 4, dv = lin & 15;
        float4 vq = qp4[lin];
        float* dst = Qt + (4 * dv) * QSTRIDE + row;
        dst[0 * QSTRIDE] = vq.x;
        dst[1 * QSTRIDE] = vq.y;
        dst[2 * QSTRIDE] = vq.z;
        dst[3 * QSTRIDE] = vq.w;
    }
    if (tid < 128) { Zs[tid] = 0.0; As[tid] = 0.0; }

    // prefetch K tile 0 (swizzled at 16B granularity)
    for (int lin = tid; lin < 2048; lin += 256) {
        int r = lin >> 4, dv = lin & 15;
        cp_async16(smem_u32(&Ks4[(r << 4) + (dv ^ (r & 15))]), &kp4[lin]);
    }
    cp_commit();

    float row_m[8];
#pragma unroll
    for (int i = 0; i < 8; i++) row_m[i] = -1e30f;

    const int NT = SHALF / 128;   // 8 tiles
    for (int kt = 0; kt < NT; kt++) {
        if (kt + 1 < NT) {
            const float4* ktp4 = kp4 + (size_t)(kt + 1) * 2048;
            float4* dst = Ks4 + ((kt + 1) & 1) * 2048;
            for (int lin = tid; lin < 2048; lin += 256) {
                int r = lin >> 4, dv = lin & 15;
                cp_async16(smem_u32(&dst[(r << 4) + (dv ^ (r & 15))]), &ktp4[lin]);
            }
            cp_commit();
            cp_wait<1>();
        } else {
            cp_wait<0>();
        }
        __syncthreads();

        const float4* Kb = Ks4 + (kt & 1) * 2048;

        unsigned long long acc2[4][8];   // row-pairs (8ty+2p, 8ty+2p+1) x 8 cols
#pragma unroll
        for (int p = 0; p < 4; p++)
#pragma unroll
            for (int j = 0; j < 8; j++) acc2[p][j] = 0ULL;

#pragma unroll 4
        for (int dv = 0; dv < 16; dv++) {
            const float4* Kbase = Kb + (tx << 4) + (dv ^ tx);
            float4 kv[8];
#pragma unroll
            for (int j = 0; j < 8; j++) kv[j] = Kbase[j << 8];

            const float* Qb = Qt + (4 * dv) * QSTRIDE + 8 * ty;
#pragma unroll
            for (int dsub = 0; dsub < 4; dsub++) {
                float4 qa = *(const float4*)(Qb + dsub * QSTRIDE);
                float4 qb = *(const float4*)(Qb + dsub * QSTRIDE + 4);
                unsigned long long q01 = pack2(qa.x, qa.y);
                unsigned long long q23 = pack2(qa.z, qa.w);
                unsigned long long q45 = pack2(qb.x, qb.y);
                unsigned long long q67 = pack2(qb.z, qb.w);
#pragma unroll
                for (int j = 0; j < 8; j++) {
                    float ks = ((const float*)&kv[j])[dsub];
                    unsigned long long kb2 = pack2(ks, ks);
                    ffma2(acc2[0][j], q01, kb2);
                    ffma2(acc2[1][j], q23, kb2);
                    ffma2(acc2[2][j], q45, kb2);
                    ffma2(acc2[3][j], q67, kb2);
                }
            }
        }

#pragma unroll
        for (int i = 0; i < 8; i++) {
            const int p = i >> 1;
            const int r = 8 * ty + i;
            float sv[8];
#pragma unroll
            for (int j = 0; j < 8; j++) {
                float2 u = unpack2(acc2[p][j]);
                sv[j] = (i & 1) ? u.y : u.x;
            }
            float tmax = -1e30f;
#pragma unroll
            for (int j = 0; j < 8; j++) {
                float s = fminf(fmaxf(sv[j] * SCALE, -50.f), 50.f);
                sv[j] = s;
                tmax = fmaxf(tmax, s);
            }
#pragma unroll
            for (int o = 8; o >= 1; o >>= 1)
                tmax = fmaxf(tmax, __shfl_xor_sync(0xffffffffu, tmax, o));

            float newm = fmaxf(row_m[i], tmax);
            float zt = 0.f, at = 0.f;
#pragma unroll
            for (int j = 0; j < 8; j++) {
                float pp = sv[j] - newm;
                float e = __expf(pp);
                zt += e;
                at = fmaf(e, pp, at);
            }
#pragma unroll
            for (int o = 8; o >= 1; o >>= 1) {
                zt += __shfl_xor_sync(0xffffffffu, zt, o);
                at += __shfl_xor_sync(0xffffffffu, at, o);
            }
            float dm = row_m[i] - newm;
            if (tx == 0) {
                double f = (double)__expf(dm);
                double Zold = Zs[r], Aold = As[r];
                Zs[r] = f * Zold + (double)zt;
                As[r] = f * (Aold + (double)dm * Zold) + (double)at;
            }
            row_m[i] = newm;
        }
        __syncthreads();
    }

    if (tx == 0) {
#pragma unroll
        for (int i = 0; i < 8; i++) {
            const int r = 8 * ty + i;
            size_t idx = (size_t)sh * (BH * T_) + (size_t)bh * T_ + q0 + r;
            g_m[idx]  = row_m[i];
            g_Zd[idx] = Zs[r];
            g_Ad[idx] = As[r];
        }
    }
}

// ---------------------------------------------------------------------------
// Phase 2: merge halves (exact double merge), KL, exact top-u radix select.
// ---------------------------------------------------------------------------
__global__ void topk_kernel(int u)
{
    const int bh = blockIdx.x;
    const int tid = threadIdx.x;   // 256
    __shared__ unsigned keys[T_];
    __shared__ int hist[256];
    __shared__ int sums[256];
    __shared__ int sh_digit, sh_need;

    for (int t = tid; t < T_; t += 256) {
        size_t i0 = (size_t)bh * T_ + t;
        size_t i1 = (size_t)BH * T_ + i0;
        double m0 = (double)g_m[i0], m1 = (double)g_m[i1];
        double m = fmax(m0, m1);
        double e0 = exp(m0 - m), e1 = exp(m1 - m);
        double Z0 = g_Zd[i0], Z1 = g_Zd[i1];
        double Z = e0 * Z0 + e1 * Z1;
        double A = e0 * (g_Ad[i0] + (m0 - m) * Z0)
                 + e1 * (g_Ad[i1] + (m1 - m) * Z1);
        float klf = (float)(A / Z - log(Z) + LOGS);
        unsigned b = __float_as_uint(klf);
        keys[t] = (b & 0x80000000u) ? ~b : (b | 0x80000000u);
    }
    __syncthreads();

    unsigned prefix = 0u, pmask = 0u;
    int need = u;
    for (int shift = 24; shift >= 0; shift -= 8) {
        hist[tid] = 0;
        __syncthreads();
        for (int t = tid; t < T_; t += 256) {
            unsigned kk = keys[t];
            if ((kk & pmask) == prefix)
                atomicAdd(&hist[(kk >> shift) & 255u], 1);
        }
        __syncthreads();
        if (tid == 0) {
            int cum = 0, d = 255;
            for (; d > 0; d--) {
                if (cum + hist[d] >= need) break;
                cum += hist[d];
            }
            sh_digit = d;
            sh_need  = need - cum;
        }
        __syncthreads();
        prefix |= ((unsigned)sh_digit) << shift;
        pmask  |= (255u << shift);
        need = sh_need;
        __syncthreads();
    }
    const unsigned thr = prefix;
    const int tie_take = need;

    const int base = tid * (T_ / 256);
    bool gtf[8], eqf[8];
    int cnt_eq = 0;
#pragma unroll
    for (int i = 0; i < 8; i++) {
        unsigned kk = keys[base + i];
        gtf[i] = (kk > thr);
        eqf[i] = (kk == thr);
        cnt_eq += eqf[i] ? 1 : 0;
    }
    sums[tid] = cnt_eq; __syncthreads();
    for (int off = 1; off < 256; off <<= 1) {
        int x = (tid >= off) ? sums[tid - off] : 0;
        __syncthreads();
        sums[tid] += x;
        __syncthreads();
    }
    int eqr = sums[tid] - cnt_eq;
    __syncthreads();

    bool self[8];
    int cnt_sel = 0;
#pragma unroll
    for (int i = 0; i < 8; i++) {
        bool s = gtf[i] || (eqf[i] && (eqr < tie_take));
        if (eqf[i]) eqr++;
        self[i] = s;
        cnt_sel += s ? 1 : 0;
    }
    sums[tid] = cnt_sel; __syncthreads();
    for (int off = 1; off < 256; off <<= 1) {
        int x = (tid >= off) ? sums[tid - off] : 0;
        __syncthreads();
        sums[tid] += x;
        __syncthreads();
    }
    int pos = sums[tid] - cnt_sel;
#pragma unroll
    for (int i = 0; i < 8; i++)
        if (self[i]) g_sel[bh * SEL_STRIDE + pos++] = base + i;
}

// ---------------------------------------------------------------------------
// Phase 3: sparse attention. 64q x 64k tiles, 4 rows x 4 cols per thread.
// QK: row-pair FFMA2 via transposed gathered Q. PV: output-pair FFMA2.
// Carveout hint aims for 3 CTAs/SM -> 320 blocks in ONE wave.
// ---------------------------------------------------------------------------
__global__ __launch_bounds__(256, 3)
void attn_kernel(const float* __restrict__ q, const float* __restrict__ k,
                 const float* __restrict__ v, float* __restrict__ out, int u)
{
    extern __shared__ char smemraw[];
    float*  Qt  = (float*)smemraw;                          // 64*68 floats (17408 B)
    float4* KP4 = (float4*)(smemraw + 64 * QSTRIDE_A * 4);  // 1024 float4 (16 KB)
    float4* Vs4 = KP4 + 1024;                               // 1024 float4 (16 KB)

    const int tid = threadIdx.x;
    const int tx = tid & 15, ty = tid >> 4;
    const int bh = blockIdx.y;
    const int q0 = blockIdx.x * 64;

    const int*    selp = g_sel + bh * SEL_STRIDE;
    const float4* kb4  = (const float4*)(k + (size_t)bh * S_ * D_);
    const float4* vb4  = (const float4*)(v + (size_t)bh * S_ * D_);
    const float4* qg4  = (const float4*)q;

    // gather + transpose selected Q rows into Qt[d][row]
    for (int lin = tid; lin < 1024; lin += 256) {
        int row = lin >> 4, dv = lin & 15;
        int qi = q0 + row;
        float4 vq = make_float4(0.f, 0.f, 0.f, 0.f);
        if (qi < u) vq = qg4[((size_t)bh * T_ + selp[qi]) * 16 + dv];
        float* dst = Qt + (4 * dv) * QSTRIDE_A + row;
        dst[0 * QSTRIDE_A] = vq.x;
        dst[1 * QSTRIDE_A] = vq.y;
        dst[2 * QSTRIDE_A] = vq.z;
        dst[3 * QSTRIDE_A] = vq.w;
    }

    float row_m[4], row_Z[4];
    unsigned long long Oxy[4], Ozw[4];
#pragma unroll
    for (int i = 0; i < 4; i++) {
        row_m[i] = -1e30f; row_Z[i] = 0.f;
        Oxy[i] = 0ULL; Ozw[i] = 0ULL;
    }

    for (int kt = 0; kt < S_ / 64; kt++) {
        __syncthreads();
        const float4* kp4 = kb4 + (size_t)kt * 64 * 16;
        const float4* vp4 = vb4 + (size_t)kt * 64 * 16;
        for (int lin = tid; lin < 1024; lin += 256) {
            int r = lin >> 4, dv = lin & 15;
            KP4[(r << 4) + (dv ^ (r & 15))] = kp4[lin];
            Vs4[lin] = vp4[lin];
        }
        __syncthreads();

        unsigned long long acc2[2][4];
#pragma unroll
        for (int p = 0; p < 2; p++)
#pragma unroll
            for (int j = 0; j < 4; j++) acc2[p][j] = 0ULL;

#pragma unroll 4
        for (int dv = 0; dv < 16; dv++) {
            const float4* Kbase = KP4 + (tx << 4) + (dv ^ tx);
            float4 kv[4];
#pragma unroll
            for (int j = 0; j < 4; j++) kv[j] = Kbase[j << 8];

            const float* Qb = Qt + (4 * dv) * QSTRIDE_A + 4 * ty;
#pragma unroll
            for (int dsub = 0; dsub < 4; dsub++) {
                float4 qa = *(const float4*)(Qb + dsub * QSTRIDE_A);
                unsigned long long q01 = pack2(qa.x, qa.y);
                unsigned long long q23 = pack2(qa.z, qa.w);
#pragma unroll
                for (int j = 0; j < 4; j++) {
                    float ks = ((const float*)&kv[j])[dsub];
                    unsigned long long kb2 = pack2(ks, ks);
                    ffma2(acc2[0][j], q01, kb2);
                    ffma2(acc2[1][j], q23, kb2);
                }
            }
        }

        float p[4][4];
#pragma unroll
        for (int i = 0; i < 4; i++) {
            const int pp = i >> 1;
            float sv[4];
#pragma unroll
            for (int j = 0; j < 4; j++) {
                float2 uu = unpack2(acc2[pp][j]);
                sv[j] = (i & 1) ? uu.y : uu.x;
            }
            float tmax = -1e30f;
#pragma unroll
            for (int j = 0; j < 4; j++) {
                float s = fminf(fmaxf(sv[j] * SCALE, -50.f), 50.f);
                sv[j] = s;
                tmax = fmaxf(tmax, s);
            }
#pragma unroll
            for (int o = 8; o >= 1; o >>= 1)
                tmax = fmaxf(tmax, __shfl_xor_sync(0xffffffffu, tmax, o));

            float newm = fmaxf(row_m[i], tmax);
            float f = __expf(row_m[i] - newm);
            float zt = 0.f;
#pragma unroll
            for (int j = 0; j < 4; j++) {
                float e = __expf(sv[j] - newm);
                p[i][j] = e;
                zt += e;
            }
#pragma unroll
            for (int o = 8; o >= 1; o >>= 1)
                zt += __shfl_xor_sync(0xffffffffu, zt, o);

            row_Z[i] = row_Z[i] * f + zt;
            unsigned long long f2 = pack2(f, f);
            asm("mul.rn.f32x2 %0, %0, %1;" : "+l"(Oxy[i]) : "l"(f2));
            asm("mul.rn.f32x2 %0, %0, %1;" : "+l"(Ozw[i]) : "l"(f2));
            row_m[i] = newm;
        }
        __syncthreads();

        float* Pf = (float*)KP4;
#pragma unroll
        for (int i = 0; i < 4; i++)
#pragma unroll
            for (int j = 0; j < 4; j++)
                Pf[((4 * ty + i) << 6) + tx + 16 * j] = p[i][j];
        __syncthreads();

#pragma unroll 4
        for (int kkv = 0; kkv < 16; kkv++) {
            float4 pv[4], vv[4];
#pragma unroll
            for (int i = 0; i < 4; i++) pv[i] = KP4[((4 * ty + i) << 4) + kkv];
#pragma unroll
            for (int m = 0; m < 4; m++) vv[m] = Vs4[((4 * kkv + m) << 4) + tx];
#pragma unroll
            for (int m = 0; m < 4; m++) {
                unsigned long long vxy = pack2(vv[m].x, vv[m].y);
                unsigned long long vzw = pack2(vv[m].z, vv[m].w);
#pragma unroll
                for (int i = 0; i < 4; i++) {
                    float pb = ((const float*)&pv[i])[m];
                    unsigned long long pb2 = pack2(pb, pb);
                    ffma2(Oxy[i], pb2, vxy);
                    ffma2(Ozw[i], pb2, vzw);
                }
            }
        }
    }

#pragma unroll
    for (int i = 0; i < 4; i++) {
        int qi = q0 + 4 * ty + i;
        if (qi < u) {
            int t = selp[qi];
            float inv = 1.0f / row_Z[i];
            float2 oxy = unpack2(Oxy[i]);
            float2 ozw = unpack2(Ozw[i]);
            float4 o = make_float4(oxy.x * inv, oxy.y * inv,
                                   ozw.x * inv, ozw.y * inv);
            float4* op4 = (float4*)(out + ((size_t)bh * T_ + t) * D_);
            op4[tx] = o;
        }
    }
}

// ---------------------------------------------------------------------------
extern "C" void kernel_launch(void* const* d_in, const int* in_sizes, int n_in,
                              void* d_out, int out_size)
{
    (void)in_sizes; (void)n_in;
    const float* q = (const float*)d_in[0];
    const float* k = (const float*)d_in[1];
    const float* v = (const float*)d_in[2];
    float* out = (float*)d_out;

    const int kl_smem   = 64 * QSTRIDE * 4 + 2 * 2048 * 16 + 256 * 8;  // ~101 KB
    const int attn_smem = 64 * QSTRIDE_A * 4 + 2 * 1024 * 16;          // ~50 KB
    cudaFuncSetAttribute(kl_kernel, cudaFuncAttributeMaxDynamicSharedMemorySize,
                         kl_smem);
    cudaFuncSetAttribute(attn_kernel, cudaFuncAttributeMaxDynamicSharedMemorySize,
                         attn_smem);
    // Force max L1/shared carveout so 3 attn CTAs (3 x 50KB) fit per SM:
    cudaFuncSetAttribute(attn_kernel, cudaFuncAttributePreferredSharedMemoryCarveout,
                         100);
    cudaFuncSetAttribute(kl_kernel, cudaFuncAttributePreferredSharedMemoryCarveout,
                         100);

    cudaMemsetAsync(d_out, 0, (size_t)out_size * sizeof(float), 0);

    dim3 g1(T_ / 128, BH, 2);
    kl_kernel<<<g1, 256, kl_smem>>>(q, k);

    topk_kernel<<<BH, 256>>>(U_SEL);

    dim3 g3((U_SEL + 63) / 64, BH);
    attn_kernel<<<g3, 256, attn_smem>>>(q, k, v, out, U_SEL);
}

// round 11
// speedup vs baseline: 1.6066x; 1.0645x over previous
#include <cuda_runtime.h>
#include <math.h>
#include <stdint.h>

#define B_    2
#define H_    16
#define BH    32
#define T_    2048
#define S_    2048
#define D_    64
#define U_SEL 614        // max(int(min(0.4*ln(2048),1024)), int(0.3*2048)) = max(3,614)
#define SEL_STRIDE 640
#define SCALE 0.125f     // 1/sqrt(64)
#define LOGS  7.624618986159398  // log(2048)
#define SHALF 1024       // S per split half
#define QSTRIDE 132      // kl Qt row stride (floats)
#define QSTRIDE_A 68     // attn Qt stride

__device__ int    g_sel[BH * SEL_STRIDE];
__device__ float  g_m[2 * BH * T_];
__device__ double g_Zd[2 * BH * T_];
__device__ double g_Ad[2 * BH * T_];

// attn kv-split scratch: [half][bh][qslot] -> O (unnormalized), m, Z
__device__ float g_Oh[2 * BH * SEL_STRIDE * D_];
__device__ float g_mh[2 * BH * SEL_STRIDE];
__device__ float g_Zh[2 * BH * SEL_STRIDE];

// ---------------------------------------------------------------------------
// helpers
// ---------------------------------------------------------------------------
__device__ __forceinline__ uint32_t smem_u32(const void* p) {
    return (uint32_t)__cvta_generic_to_shared(p);
}
__device__ __forceinline__ void cp_async16(uint32_t dst, const void* src) {
    asm volatile("cp.async.cg.shared.global [%0], [%1], 16;\n" :: "r"(dst), "l"(src));
}
__device__ __forceinline__ void cp_commit() {
    asm volatile("cp.async.commit_group;\n");
}
template <int N>
__device__ __forceinline__ void cp_wait() {
    asm volatile("cp.async.wait_group %0;\n" :: "n"(N));
}

// packed f32x2 ops (Blackwell): 2 fp32 FMAs per issue slot
__device__ __forceinline__ unsigned long long pack2(float lo, float hi) {
    unsigned long long r;
    asm("mov.b64 %0, {%1, %2};" : "=l"(r) : "f"(lo), "f"(hi));
    return r;
}
__device__ __forceinline__ void ffma2(unsigned long long& d,
                                      unsigned long long a, unsigned long long b) {
    asm("fma.rn.f32x2 %0, %1, %2, %3;" : "=l"(d) : "l"(a), "l"(b), "l"(d));
}
__device__ __forceinline__ float2 unpack2(unsigned long long a) {
    float lo, hi;
    asm("mov.b64 {%0, %1}, %2;" : "=f"(lo), "=f"(hi) : "l"(a));
    return make_float2(lo, hi);
}

// ---------------------------------------------------------------------------
// Phase 1: partial online-softmax KL stats (unchanged, proven 488us).
// 128q x 128k tile, 8x8 thread tile in f32x2 row-pairs, 2 CTAs/SM.
// ---------------------------------------------------------------------------
__global__ __launch_bounds__(256, 2)
void kl_kernel(const float* __restrict__ q, const float* __restrict__ k)
{
    extern __shared__ char smemraw[];
    float*  Qt  = (float*)smemraw;                        // 64*132 floats
    float4* Ks4 = (float4*)(smemraw + 64 * QSTRIDE * 4);  // 2*2048 float4
    double* Zs  = (double*)(smemraw + 64 * QSTRIDE * 4 + 2 * 2048 * 16);
    double* As  = Zs + 128;

    const int tid = threadIdx.x;
    const int tx = tid & 15, ty = tid >> 4;
    const int bh = blockIdx.y;
    const int q0 = blockIdx.x * 128;
    const int sh = blockIdx.z;

    const float4* qp4 = (const float4*)(q + ((size_t)bh * T_ + q0) * D_);
    const float4* kp4 = (const float4*)(k + ((size_t)bh * S_ + sh * SHALF) * D_);

    for (int lin = tid; lin < 2048; lin += 256) {
        int row = lin >> 4, dv = lin & 15;
        float4 vq = qp4[lin];
        float* dst = Qt + (4 * dv) * QSTRIDE + row;
        dst[0 * QSTRIDE] = vq.x;
        dst[1 * QSTRIDE] = vq.y;
        dst[2 * QSTRIDE] = vq.z;
        dst[3 * QSTRIDE] = vq.w;
    }
    if (tid < 128) { Zs[tid] = 0.0; As[tid] = 0.0; }

    for (int lin = tid; lin < 2048; lin += 256) {
        int r = lin >> 4, dv = lin & 15;
        cp_async16(smem_u32(&Ks4[(r << 4) + (dv ^ (r & 15))]), &kp4[lin]);
    }
    cp_commit();

    float row_m[8];
#pragma unroll
    for (int i = 0; i < 8; i++) row_m[i] = -1e30f;

    const int NT = SHALF / 128;
    for (int kt = 0; kt < NT; kt++) {
        if (kt + 1 < NT) {
            const float4* ktp4 = kp4 + (size_t)(kt + 1) * 2048;
            float4* dst = Ks4 + ((kt + 1) & 1) * 2048;
            for (int lin = tid; lin < 2048; lin += 256) {
                int r = lin >> 4, dv = lin & 15;
                cp_async16(smem_u32(&dst[(r << 4) + (dv ^ (r & 15))]), &ktp4[lin]);
            }
            cp_commit();
            cp_wait<1>();
        } else {
            cp_wait<0>();
        }
        __syncthreads();

        const float4* Kb = Ks4 + (kt & 1) * 2048;

        unsigned long long acc2[4][8];
#pragma unroll
        for (int p = 0; p < 4; p++)
#pragma unroll
            for (int j = 0; j < 8; j++) acc2[p][j] = 0ULL;

#pragma unroll 4
        for (int dv = 0; dv < 16; dv++) {
            const float4* Kbase = Kb + (tx << 4) + (dv ^ tx);
            float4 kv[8];
#pragma unroll
            for (int j = 0; j < 8; j++) kv[j] = Kbase[j << 8];

            const float* Qb = Qt + (4 * dv) * QSTRIDE + 8 * ty;
#pragma unroll
            for (int dsub = 0; dsub < 4; dsub++) {
                float4 qa = *(const float4*)(Qb + dsub * QSTRIDE);
                float4 qb = *(const float4*)(Qb + dsub * QSTRIDE + 4);
                unsigned long long q01 = pack2(qa.x, qa.y);
                unsigned long long q23 = pack2(qa.z, qa.w);
                unsigned long long q45 = pack2(qb.x, qb.y);
                unsigned long long q67 = pack2(qb.z, qb.w);
#pragma unroll
                for (int j = 0; j < 8; j++) {
                    float ks = ((const float*)&kv[j])[dsub];
                    unsigned long long kb2 = pack2(ks, ks);
                    ffma2(acc2[0][j], q01, kb2);
                    ffma2(acc2[1][j], q23, kb2);
                    ffma2(acc2[2][j], q45, kb2);
                    ffma2(acc2[3][j], q67, kb2);
                }
            }
        }

#pragma unroll
        for (int i = 0; i < 8; i++) {
            const int p = i >> 1;
            const int r = 8 * ty + i;
            float sv[8];
#pragma unroll
            for (int j = 0; j < 8; j++) {
                float2 u = unpack2(acc2[p][j]);
                sv[j] = (i & 1) ? u.y : u.x;
            }
            float tmax = -1e30f;
#pragma unroll
            for (int j = 0; j < 8; j++) {
                float s = fminf(fmaxf(sv[j] * SCALE, -50.f), 50.f);
                sv[j] = s;
                tmax = fmaxf(tmax, s);
            }
#pragma unroll
            for (int o = 8; o >= 1; o >>= 1)
                tmax = fmaxf(tmax, __shfl_xor_sync(0xffffffffu, tmax, o));

            float newm = fmaxf(row_m[i], tmax);
            float zt = 0.f, at = 0.f;
#pragma unroll
            for (int j = 0; j < 8; j++) {
                float pp = sv[j] - newm;
                float e = __expf(pp);
                zt += e;
                at = fmaf(e, pp, at);
            }
#pragma unroll
            for (int o = 8; o >= 1; o >>= 1) {
                zt += __shfl_xor_sync(0xffffffffu, zt, o);
                at += __shfl_xor_sync(0xffffffffu, at, o);
            }
            float dm = row_m[i] - newm;
            if (tx == 0) {
                double f = (double)__expf(dm);
                double Zold = Zs[r], Aold = As[r];
                Zs[r] = f * Zold + (double)zt;
                As[r] = f * (Aold + (double)dm * Zold) + (double)at;
            }
            row_m[i] = newm;
        }
        __syncthreads();
    }

    if (tx == 0) {
#pragma unroll
        for (int i = 0; i < 8; i++) {
            const int r = 8 * ty + i;
            size_t idx = (size_t)sh * (BH * T_) + (size_t)bh * T_ + q0 + r;
            g_m[idx]  = row_m[i];
            g_Zd[idx] = Zs[r];
            g_Ad[idx] = As[r];
        }
    }
}

// ---------------------------------------------------------------------------
// Phase 2: merge halves (exact double merge), KL, exact top-u radix select.
// ---------------------------------------------------------------------------
__global__ void topk_kernel(int u)
{
    const int bh = blockIdx.x;
    const int tid = threadIdx.x;   // 256
    __shared__ unsigned keys[T_];
    __shared__ int hist[256];
    __shared__ int sums[256];
    __shared__ int sh_digit, sh_need;

    for (int t = tid; t < T_; t += 256) {
        size_t i0 = (size_t)bh * T_ + t;
        size_t i1 = (size_t)BH * T_ + i0;
        double m0 = (double)g_m[i0], m1 = (double)g_m[i1];
        double m = fmax(m0, m1);
        double e0 = exp(m0 - m), e1 = exp(m1 - m);
        double Z0 = g_Zd[i0], Z1 = g_Zd[i1];
        double Z = e0 * Z0 + e1 * Z1;
        double A = e0 * (g_Ad[i0] + (m0 - m) * Z0)
                 + e1 * (g_Ad[i1] + (m1 - m) * Z1);
        float klf = (float)(A / Z - log(Z) + LOGS);
        unsigned b = __float_as_uint(klf);
        keys[t] = (b & 0x80000000u) ? ~b : (b | 0x80000000u);
    }
    __syncthreads();

    unsigned prefix = 0u, pmask = 0u;
    int need = u;
    for (int shift = 24; shift >= 0; shift -= 8) {
        hist[tid] = 0;
        __syncthreads();
        for (int t = tid; t < T_; t += 256) {
            unsigned kk = keys[t];
            if ((kk & pmask) == prefix)
                atomicAdd(&hist[(kk >> shift) & 255u], 1);
        }
        __syncthreads();
        if (tid == 0) {
            int cum = 0, d = 255;
            for (; d > 0; d--) {
                if (cum + hist[d] >= need) break;
                cum += hist[d];
            }
            sh_digit = d;
            sh_need  = need - cum;
        }
        __syncthreads();
        prefix |= ((unsigned)sh_digit) << shift;
        pmask  |= (255u << shift);
        need = sh_need;
        __syncthreads();
    }
    const unsigned thr = prefix;
    const int tie_take = need;

    const int base = tid * (T_ / 256);
    bool gtf[8], eqf[8];
    int cnt_eq = 0;
#pragma unroll
    for (int i = 0; i < 8; i++) {
        unsigned kk = keys[base + i];
        gtf[i] = (kk > thr);
        eqf[i] = (kk == thr);
        cnt_eq += eqf[i] ? 1 : 0;
    }
    sums[tid] = cnt_eq; __syncthreads();
    for (int off = 1; off < 256; off <<= 1) {
        int x = (tid >= off) ? sums[tid - off] : 0;
        __syncthreads();
        sums[tid] += x;
        __syncthreads();
    }
    int eqr = sums[tid] - cnt_eq;
    __syncthreads();

    bool self[8];
    int cnt_sel = 0;
#pragma unroll
    for (int i = 0; i < 8; i++) {
        bool s = gtf[i] || (eqf[i] && (eqr < tie_take));
        if (eqf[i]) eqr++;
        self[i] = s;
        cnt_sel += s ? 1 : 0;
    }
    sums[tid] = cnt_sel; __syncthreads();
    for (int off = 1; off < 256; off <<= 1) {
        int x = (tid >= off) ? sums[tid - off] : 0;
        __syncthreads();
        sums[tid] += x;
        __syncthreads();
    }
    int pos = sums[tid] - cnt_sel;
#pragma unroll
    for (int i = 0; i < 8; i++)
        if (self[i]) g_sel[bh * SEL_STRIDE + pos++] = base + i;
}

// ---------------------------------------------------------------------------
// Phase 3: sparse attention, kv-split over 2 S-halves (blockIdx.z).
// Inner loops identical to the proven R6 kernel; writes UNNORMALIZED O + m,Z
// per half to scratch. 640 blocks -> better wave balance than 320.
// ---------------------------------------------------------------------------
__global__ __launch_bounds__(256, 3)
void attn_kernel(const float* __restrict__ q, const float* __restrict__ k,
                 const float* __restrict__ v, int u)
{
    extern __shared__ char smemraw[];
    float*  Qt  = (float*)smemraw;
    float4* KP4 = (float4*)(smemraw + 64 * QSTRIDE_A * 4);
    float4* Vs4 = KP4 + 1024;

    const int tid = threadIdx.x;
    const int tx = tid & 15, ty = tid >> 4;
    const int bh = blockIdx.y;
    const int q0 = blockIdx.x * 64;
    const int sh = blockIdx.z;

    const int*    selp = g_sel + bh * SEL_STRIDE;
    const float4* kb4  = (const float4*)(k + ((size_t)bh * S_ + sh * SHALF) * D_);
    const float4* vb4  = (const float4*)(v + ((size_t)bh * S_ + sh * SHALF) * D_);
    const float4* qg4  = (const float4*)q;

    for (int lin = tid; lin < 1024; lin += 256) {
        int row = lin >> 4, dv = lin & 15;
        int qi = q0 + row;
        float4 vq = make_float4(0.f, 0.f, 0.f, 0.f);
        if (qi < u) vq = qg4[((size_t)bh * T_ + selp[qi]) * 16 + dv];
        float* dst = Qt + (4 * dv) * QSTRIDE_A + row;
        dst[0 * QSTRIDE_A] = vq.x;
        dst[1 * QSTRIDE_A] = vq.y;
        dst[2 * QSTRIDE_A] = vq.z;
        dst[3 * QSTRIDE_A] = vq.w;
    }

    float row_m[4], row_Z[4];
    unsigned long long Oxy[4], Ozw[4];
#pragma unroll
    for (int i = 0; i < 4; i++) {
        row_m[i] = -1e30f; row_Z[i] = 0.f;
        Oxy[i] = 0ULL; Ozw[i] = 0ULL;
    }

    for (int kt = 0; kt < SHALF / 64; kt++) {
        __syncthreads();
        const float4* kp4 = kb4 + (size_t)kt * 64 * 16;
        const float4* vp4 = vb4 + (size_t)kt * 64 * 16;
        for (int lin = tid; lin < 1024; lin += 256) {
            int r = lin >> 4, dv = lin & 15;
            KP4[(r << 4) + (dv ^ (r & 15))] = kp4[lin];
            Vs4[lin] = vp4[lin];
        }
        __syncthreads();

        unsigned long long acc2[2][4];
#pragma unroll
        for (int p = 0; p < 2; p++)
#pragma unroll
            for (int j = 0; j < 4; j++) acc2[p][j] = 0ULL;

#pragma unroll 4
        for (int dv = 0; dv < 16; dv++) {
            const float4* Kbase = KP4 + (tx << 4) + (dv ^ tx);
            float4 kv[4];
#pragma unroll
            for (int j = 0; j < 4; j++) kv[j] = Kbase[j << 8];

            const float* Qb = Qt + (4 * dv) * QSTRIDE_A + 4 * ty;
#pragma unroll
            for (int dsub = 0; dsub < 4; dsub++) {
                float4 qa = *(const float4*)(Qb + dsub * QSTRIDE_A);
                unsigned long long q01 = pack2(qa.x, qa.y);
                unsigned long long q23 = pack2(qa.z, qa.w);
#pragma unroll
                for (int j = 0; j < 4; j++) {
                    float ks = ((const float*)&kv[j])[dsub];
                    unsigned long long kb2 = pack2(ks, ks);
                    ffma2(acc2[0][j], q01, kb2);
                    ffma2(acc2[1][j], q23, kb2);
                }
            }
        }

        float p[4][4];
#pragma unroll
        for (int i = 0; i < 4; i++) {
            const int pp = i >> 1;
            float sv[4];
#pragma unroll
            for (int j = 0; j < 4; j++) {
                float2 uu = unpack2(acc2[pp][j]);
                sv[j] = (i & 1) ? uu.y : uu.x;
            }
            float tmax = -1e30f;
#pragma unroll
            for (int j = 0; j < 4; j++) {
                float s = fminf(fmaxf(sv[j] * SCALE, -50.f), 50.f);
                sv[j] = s;
                tmax = fmaxf(tmax, s);
            }
#pragma unroll
            for (int o = 8; o >= 1; o >>= 1)
                tmax = fmaxf(tmax, __shfl_xor_sync(0xffffffffu, tmax, o));

            float newm = fmaxf(row_m[i], tmax);
            float f = __expf(row_m[i] - newm);
            float zt = 0.f;
#pragma unroll
            for (int j = 0; j < 4; j++) {
                float e = __expf(sv[j] - newm);
                p[i][j] = e;
                zt += e;
            }
#pragma unroll
            for (int o = 8; o >= 1; o >>= 1)
                zt += __shfl_xor_sync(0xffffffffu, zt, o);

            row_Z[i] = row_Z[i] * f + zt;
            unsigned long long f2 = pack2(f, f);
            asm("mul.rn.f32x2 %0, %0, %1;" : "+l"(Oxy[i]) : "l"(f2));
            asm("mul.rn.f32x2 %0, %0, %1;" : "+l"(Ozw[i]) : "l"(f2));
            row_m[i] = newm;
        }
        __syncthreads();

        float* Pf = (float*)KP4;
#pragma unroll
        for (int i = 0; i < 4; i++)
#pragma unroll
            for (int j = 0; j < 4; j++)
                Pf[((4 * ty + i) << 6) + tx + 16 * j] = p[i][j];
        __syncthreads();

#pragma unroll 4
        for (int kkv = 0; kkv < 16; kkv++) {
            float4 pv[4], vv[4];
#pragma unroll
            for (int i = 0; i < 4; i++) pv[i] = KP4[((4 * ty + i) << 4) + kkv];
#pragma unroll
            for (int m = 0; m < 4; m++) vv[m] = Vs4[((4 * kkv + m) << 4) + tx];
#pragma unroll
            for (int m = 0; m < 4; m++) {
                unsigned long long vxy = pack2(vv[m].x, vv[m].y);
                unsigned long long vzw = pack2(vv[m].z, vv[m].w);
#pragma unroll
                for (int i = 0; i < 4; i++) {
                    float pb = ((const float*)&pv[i])[m];
                    unsigned long long pb2 = pack2(pb, pb);
                    ffma2(Oxy[i], pb2, vxy);
                    ffma2(Ozw[i], pb2, vzw);
                }
            }
        }
    }

    // write unnormalized O + per-row stats to scratch
#pragma unroll
    for (int i = 0; i < 4; i++) {
        int qi = q0 + 4 * ty + i;
        if (qi < u) {
            size_t rbase = ((size_t)sh * BH + bh) * SEL_STRIDE + qi;
            float2 oxy = unpack2(Oxy[i]);
            float2 ozw = unpack2(Ozw[i]);
            float4* op4 = (float4*)(g_Oh + rbase * D_);
            op4[tx] = make_float4(oxy.x, oxy.y, ozw.x, ozw.y);
            if (tx == 0) {
                g_mh[rbase] = row_m[i];
                g_Zh[rbase] = row_Z[i];
            }
        }
    }
}

// ---------------------------------------------------------------------------
// Phase 3b: merge the two kv-split halves and scatter to out.
// block = 64 q-slots; thread: row = tid>>2, quarter g = tid&3 (16 cols).
// ---------------------------------------------------------------------------
__global__ __launch_bounds__(256)
void attn_merge_kernel(float* __restrict__ out, int u)
{
    const int tid = threadIdx.x;
    const int bh = blockIdx.y;
    const int qi = blockIdx.x * 64 + (tid >> 2);
    const int g  = tid & 3;
    if (qi >= u) return;

    size_t r0 = (size_t)bh * SEL_STRIDE + qi;
    size_t r1 = (size_t)BH * SEL_STRIDE + r0;
    float m0 = g_mh[r0], m1 = g_mh[r1];
    float m = fmaxf(m0, m1);
    float f0 = __expf(m0 - m), f1 = __expf(m1 - m);
    float Z = f0 * g_Zh[r0] + f1 * g_Zh[r1];
    float inv = 1.0f / Z;

    const float4* O0 = (const float4*)(g_Oh + r0 * D_) + g * 4;
    const float4* O1 = (const float4*)(g_Oh + r1 * D_) + g * 4;
    int t = g_sel[bh * SEL_STRIDE + qi];
    float4* op = (float4*)(out + ((size_t)bh * T_ + t) * D_) + g * 4;
#pragma unroll
    for (int c = 0; c < 4; c++) {
        float4 a = O0[c], b = O1[c];
        op[c] = make_float4((f0 * a.x + f1 * b.x) * inv,
                            (f0 * a.y + f1 * b.y) * inv,
                            (f0 * a.z + f1 * b.z) * inv,
                            (f0 * a.w + f1 * b.w) * inv);
    }
}

// ---------------------------------------------------------------------------
extern "C" void kernel_launch(void* const* d_in, const int* in_sizes, int n_in,
                              void* d_out, int out_size)
{
    (void)in_sizes; (void)n_in;
    const float* q = (const float*)d_in[0];
    const float* k = (const float*)d_in[1];
    const float* v = (const float*)d_in[2];
    float* out = (float*)d_out;

    const int kl_smem   = 64 * QSTRIDE * 4 + 2 * 2048 * 16 + 256 * 8;  // ~101 KB
    const int attn_smem = 64 * QSTRIDE_A * 4 + 2 * 1024 * 16;          // ~50 KB
    cudaFuncSetAttribute(kl_kernel, cudaFuncAttributeMaxDynamicSharedMemorySize,
                         kl_smem);
    cudaFuncSetAttribute(attn_kernel, cudaFuncAttributeMaxDynamicSharedMemorySize,
                         attn_smem);
    cudaFuncSetAttribute(attn_kernel, cudaFuncAttributePreferredSharedMemoryCarveout,
                         100);
    cudaFuncSetAttribute(kl_kernel, cudaFuncAttributePreferredSharedMemoryCarveout,
                         100);

    cudaMemsetAsync(d_out, 0, (size_t)out_size * sizeof(float), 0);

    dim3 g1(T_ / 128, BH, 2);
    kl_kernel<<<g1, 256, kl_smem>>>(q, k);

    topk_kernel<<<BH, 256>>>(U_SEL);

    dim3 g3((U_SEL + 63) / 64, BH, 2);
    attn_kernel<<<g3, 256, attn_smem>>>(q, k, v, U_SEL);

    dim3 g4((U_SEL + 63) / 64, BH);
    attn_merge_kernel<<<g4, 256>>>(out, U_SEL);
}